// round 14
// baseline (speedup 1.0000x reference)
#include <cuda_runtime.h>

#define NN 50000
#define EE 800000
#define BBATCH 256
#define TSTEPS 50
#define FM 0xffffffffu

__device__ __align__(16) float d_xw[NN*128];
__device__ __align__(16) float d_h[NN*128];
__device__ __align__(16) float d_hw[NN*128];
__device__ __align__(16) float d_asrc[NN*4];
__device__ __align__(16) float d_adst[NN*4];
__device__ float d_dinv[NN];
__device__ int   d_deg[NN];
__device__ int   d_rowptr[NN+1];
__device__ int   d_cursor[NN];
__device__ int   d_colsrc[EE];
__device__ int   d_bsum[256], d_boff[256];
__device__ float d_gnum[BBATCH*128];
__device__ float d_gden[BBATCH];
__device__ __align__(16) float d_xp[BBATCH*TSTEPS*512];
__device__ float d_hT[BBATCH*128];

__device__ __forceinline__ float sigf(float x){ return __fdividef(1.f, 1.f + __expf(-x)); }
__device__ __forceinline__ float tanhfa(float x){ float e=__expf(2.f*x); return 1.f - __fdividef(2.f, e+1.f); }

__device__ __forceinline__ void ffma2(unsigned long long& d, unsigned long long a, unsigned long long b){
    asm("fma.rn.f32x2 %0, %1, %2, %0;" : "+l"(d) : "l"(a), "l"(b));
}
__device__ __forceinline__ unsigned long long dup2(float x){
    unsigned long long r;
    asm("mov.b64 %0, {%1, %1};" : "=l"(r) : "f"(x));
    return r;
}
__device__ __forceinline__ float pairsum(unsigned long long v){
    float2 f; __builtin_memcpy(&f, &v, 8); return f.x + f.y;
}
__device__ __forceinline__ float2 unpack2(unsigned long long v){
    float2 f; __builtin_memcpy(&f, &v, 8); return f;
}

__global__ void k_init(){
    int i = blockIdx.x*256 + threadIdx.x;
    if (i < NN) d_deg[i] = 0;
    if (i < BBATCH*128) d_gnum[i]=0.f;
    if (i < BBATCH) d_gden[i]=0.f;
}

__global__ void k_count(const int* __restrict__ ei){
    int i = blockIdx.x*256 + threadIdx.x;
    if (i < EE) atomicAdd(&d_deg[ei[EE+i]], 1);
}

__global__ void k_scan1(){
    __shared__ int s[256];
    int tid = threadIdx.x;
    int i = blockIdx.x*256 + tid;
    int v = (i < NN) ? d_deg[i] : 0;
    s[tid] = v; __syncthreads();
    for (int off=1; off<256; off<<=1){
        int t = (tid>=off) ? s[tid-off] : 0;
        __syncthreads(); s[tid] += t; __syncthreads();
    }
    if (i < NN) d_rowptr[i+1] = s[tid];
    if (tid == 255) d_bsum[blockIdx.x] = s[255];
}

__global__ void k_scan2(){
    __shared__ int s[256];
    int tid = threadIdx.x;
    int v = (tid < 196) ? d_bsum[tid] : 0;
    s[tid] = v; __syncthreads();
    for (int off=1; off<256; off<<=1){
        int t = (tid>=off) ? s[tid-off] : 0;
        __syncthreads(); s[tid] += t; __syncthreads();
    }
    if (tid < 196) d_boff[tid] = s[tid] - v;
}

__global__ void k_scan3(){
    int i = blockIdx.x*256 + threadIdx.x;
    if (i < NN) d_rowptr[i+1] += d_boff[blockIdx.x];
    if (i == 0) d_rowptr[0] = 0;
}

__global__ void k_prep(){
    int i = blockIdx.x*256 + threadIdx.x;
    if (i >= NN) return;
    int a = d_rowptr[i], b = d_rowptr[i+1];
    d_cursor[i] = a;
    d_dinv[i] = rsqrtf((float)(b - a + 1));
}

__global__ void k_scatter(const int* __restrict__ ei){
    int i = blockIdx.x*256 + threadIdx.x;
    if (i >= EE) return;
    int s = ei[i], d = ei[EE+i];
    int pos = atomicAdd(&d_cursor[d], 1);
    d_colsrc[pos] = s;
}

// GEMM v4 (unchanged)
__global__ void __launch_bounds__(256,2) k_gemm(const float* __restrict__ Xp,
                       const float* __restrict__ W,
                       const float* __restrict__ attS, const float* __restrict__ attD, int mode){
    extern __shared__ float sm[];
    float* Ws = sm;
    float* xs = sm + 16384;
    const float* X = mode ? d_h : Xp;
    float* Y = mode ? d_hw : d_xw;
    int tid = threadIdx.x, cg = tid & 31, rg = tid >> 5;
    for (int i = tid; i < 16384; i += 256) Ws[i] = W[i];
    float as0=0,as1=0,as2=0,as3=0, ad0=0,ad1=0,ad2=0,ad3=0;
    if (!mode){
        as0=attS[cg*4]; as1=attS[cg*4+1]; as2=attS[cg*4+2]; as3=attS[cg*4+3];
        ad0=attD[cg*4]; ad1=attD[cg*4+1]; ad2=attD[cg*4+2]; ad3=attD[cg*4+3];
    }
    __syncthreads();
    const ulonglong2* Wsp = (const ulonglong2*)Ws;
    const int nchunk = (NN + 63) / 64;
    for (int chunk = blockIdx.x; chunk < nchunk; chunk += gridDim.x){
        int row0 = chunk*64;
        __syncthreads();
        for (int i = tid; i < 8192; i += 256){
            int r = i >> 7, k = i & 127;
            int gr = row0 + r;
            xs[i] = (gr < NN) ? X[gr*128 + k] : 0.f;
        }
        __syncthreads();
        unsigned long long acc[8][2];
        #pragma unroll
        for (int r=0;r<8;r++){ acc[r][0]=0ull; acc[r][1]=0ull; }
        const float* xb = xs + rg*8*128;
        #pragma unroll 4
        for (int k2=0;k2<64;k2++){
            int k = k2*2;
            ulonglong2 w0 = Wsp[k*32 + cg];
            ulonglong2 w1 = Wsp[(k+1)*32 + cg];
            #pragma unroll
            for (int r=0;r<8;r++){
                float2 xv = *(const float2*)&xb[r*128 + k];
                unsigned long long xa = dup2(xv.x);
                unsigned long long xc = dup2(xv.y);
                ffma2(acc[r][0], xa, w0.x); ffma2(acc[r][1], xa, w0.y);
                ffma2(acc[r][0], xc, w1.x); ffma2(acc[r][1], xc, w1.y);
            }
        }
        #pragma unroll
        for (int r=0;r<8;r++){
            int grow = row0 + rg*8 + r;
            float2 p01 = unpack2(acc[r][0]);
            float2 p23 = unpack2(acc[r][1]);
            if (grow < NN)
                *(float4*)&Y[grow*128 + cg*4] = make_float4(p01.x,p01.y,p23.x,p23.y);
            if (!mode){
                float s = p01.x*as0 + p01.y*as1 + p23.x*as2 + p23.y*as3;
                float d = p01.x*ad0 + p01.y*ad1 + p23.x*ad2 + p23.y*ad3;
                #pragma unroll
                for (int off=4; off; off>>=1){
                    s += __shfl_xor_sync(FM, s, off);
                    d += __shfl_xor_sync(FM, d, off);
                }
                if ((cg & 7) == 0 && grow < NN){
                    d_asrc[grow*4 + (cg>>3)] = s;
                    d_adst[grow*4 + (cg>>3)] = d;
                }
            }
        }
    }
}

// GAT aggregation v2 (unchanged from R13)
__global__ void k_gat(const float* __restrict__ gatb,
                      const float* __restrict__ g1, const float* __restrict__ b1,
                      const float* __restrict__ m1, const float* __restrict__ v1){
    __shared__ float sc[128], sh[128], gb[128];
    __shared__ int   sjs[8][32];
    __shared__ __align__(16) float sex[8][32][4];
    int tid = threadIdx.x;
    if (tid < 128){
        float s = g1[tid]*rsqrtf(v1[tid]+1e-5f);
        sc[tid]=s; sh[tid]=b1[tid]-m1[tid]*s; gb[tid]=gatb[tid];
    }
    __syncthreads();
    int lane = tid & 31, w = tid >> 5;
    int node = blockIdx.x*8 + w;
    if (node >= NN) return;
    int begin = d_rowptr[node], end = d_rowptr[node+1];
    float4 adv = *(const float4*)&d_adst[node*4];
    unsigned long long a01 = 0ull, a23 = 0ull;
    float dn0=0,dn1=0,dn2=0,dn3=0;
    for (int base = begin; base < end; base += 32){
        int idx = base + lane;
        int sl = 0; float4 exl = make_float4(0,0,0,0);
        if (idx < end){
            sl = d_colsrc[idx];
            float4 as = *(const float4*)&d_asrc[sl*4];
            float e0 = as.x+adv.x; e0 = e0>0.f? e0 : 0.2f*e0;
            float e1 = as.y+adv.y; e1 = e1>0.f? e1 : 0.2f*e1;
            float e2 = as.z+adv.z; e2 = e2>0.f? e2 : 0.2f*e2;
            float e3 = as.w+adv.w; e3 = e3>0.f? e3 : 0.2f*e3;
            exl = make_float4(__expf(e0),__expf(e1),__expf(e2),__expf(e3));
            dn0+=exl.x; dn1+=exl.y; dn2+=exl.z; dn3+=exl.w;
        }
        sjs[w][lane] = sl;
        *(float4*)sex[w][lane] = exl;
        __syncwarp();
        int cnt = min(32, end - base);
        int sj0 = sjs[w][0];
        ulonglong2 xv = *(const ulonglong2*)&d_xw[sj0*128 + lane*4];
        for (int j=0; j<cnt; j++){
            ulonglong2 xn = xv;
            if (j+1 < cnt){
                int sjn = sjs[w][j+1];
                xn = *(const ulonglong2*)&d_xw[sjn*128 + lane*4];
            }
            unsigned long long av = dup2(sex[w][j][lane>>3]);
            ffma2(a01, xv.x, av);
            ffma2(a23, xv.y, av);
            xv = xn;
        }
        __syncwarp();
    }
    #pragma unroll
    for (int off=16; off; off>>=1){
        dn0 += __shfl_xor_sync(FM,dn0,off); dn1 += __shfl_xor_sync(FM,dn1,off);
        dn2 += __shfl_xor_sync(FM,dn2,off); dn3 += __shfl_xor_sync(FM,dn3,off);
    }
    float2 p01 = unpack2(a01), p23 = unpack2(a23);
    float n0=p01.x, n1=p01.y, n2=p23.x, n3=p23.y;
    float4 as = *(const float4*)&d_asrc[node*4];
    float e0=as.x+adv.x; e0=e0>0.f?e0:0.2f*e0; float x0=__expf(e0);
    float e1=as.y+adv.y; e1=e1>0.f?e1:0.2f*e1; float x1=__expf(e1);
    float e2=as.z+adv.z; e2=e2>0.f?e2:0.2f*e2; float x2=__expf(e2);
    float e3=as.w+adv.w; e3=e3>0.f?e3:0.2f*e3; float x3=__expf(e3);
    dn0+=x0; dn1+=x1; dn2+=x2; dn3+=x3;
    float4 xvs = *(const float4*)&d_xw[node*128 + lane*4];
    float aself = lane<8? x0 : lane<16? x1 : lane<24? x2 : x3;
    n0 += xvs.x*aself; n1 += xvs.y*aself; n2 += xvs.z*aself; n3 += xvs.w*aself;
    float hd = lane<8? dn0 : lane<16? dn1 : lane<24? dn2 : dn3;
    float inv = 1.0f/(hd + 1e-16f);
    int col = lane*4;
    float o0 = n0*inv + gb[col];   o0 = o0>0.f? o0 : expm1f(o0); o0 = o0*sc[col]+sh[col];
    float o1 = n1*inv + gb[col+1]; o1 = o1>0.f? o1 : expm1f(o1); o1 = o1*sc[col+1]+sh[col+1];
    float o2 = n2*inv + gb[col+2]; o2 = o2>0.f? o2 : expm1f(o2); o2 = o2*sc[col+2]+sh[col+2];
    float o3 = n3*inv + gb[col+3]; o3 = o3>0.f? o3 : expm1f(o3); o3 = o3*sc[col+3]+sh[col+3];
    *(float4*)&d_h[node*128 + col] = make_float4(o0,o1,o2,o3);
}

// GCN aggregation v2 (unchanged from R13)
__global__ void k_gcn(const int* __restrict__ batch,
                      const float* __restrict__ gcnb,
                      const float* __restrict__ g2, const float* __restrict__ b2,
                      const float* __restrict__ m2, const float* __restrict__ v2,
                      const float* __restrict__ gateW, const float* __restrict__ gateb){
    __shared__ float sc[128], sh[128], gb[128], gw[128];
    __shared__ int   sjs[8][32];
    __shared__ float sds[8][32];
    int tid = threadIdx.x;
    if (tid < 128){
        float s = g2[tid]*rsqrtf(v2[tid]+1e-5f);
        sc[tid]=s; sh[tid]=b2[tid]-m2[tid]*s; gb[tid]=gcnb[tid]; gw[tid]=gateW[tid];
    }
    __syncthreads();
    int lane = tid & 31, w = tid >> 5;
    int node = blockIdx.x*8 + w;
    if (node >= NN) return;
    int begin = d_rowptr[node], end = d_rowptr[node+1];
    float did = d_dinv[node];
    unsigned long long a01 = 0ull, a23 = 0ull;
    for (int base = begin; base < end; base += 32){
        int idx = base + lane;
        int sl = 0; float dsl = 0.f;
        if (idx < end){ sl = d_colsrc[idx]; dsl = d_dinv[sl]; }
        sjs[w][lane] = sl;
        sds[w][lane] = dsl;
        __syncwarp();
        int cnt = min(32, end - base);
        int sj0 = sjs[w][0];
        ulonglong2 xv = *(const ulonglong2*)&d_hw[sj0*128 + lane*4];
        for (int j=0; j<cnt; j++){
            ulonglong2 xn = xv;
            if (j+1 < cnt){
                int sjn = sjs[w][j+1];
                xn = *(const ulonglong2*)&d_hw[sjn*128 + lane*4];
            }
            unsigned long long dv = dup2(sds[w][j]);
            ffma2(a01, xv.x, dv);
            ffma2(a23, xv.y, dv);
            xv = xn;
        }
        __syncwarp();
    }
    float2 p01 = unpack2(a01), p23 = unpack2(a23);
    int col = lane*4;
    float4 sv = *(const float4*)&d_hw[node*128 + col];
    float h0 = did*(p01.x + did*sv.x) + gb[col];
    float h1 = did*(p01.y + did*sv.y) + gb[col+1];
    float h2v = did*(p23.x + did*sv.z) + gb[col+2];
    float h3 = did*(p23.y + did*sv.w) + gb[col+3];
    h0 = h0>0.f? h0 : expm1f(h0); h0 = h0*sc[col]+sh[col];
    h1 = h1>0.f? h1 : expm1f(h1); h1 = h1*sc[col+1]+sh[col+1];
    h2v = h2v>0.f? h2v : expm1f(h2v); h2v = h2v*sc[col+2]+sh[col+2];
    h3 = h3>0.f? h3 : expm1f(h3); h3 = h3*sc[col+3]+sh[col+3];
    float g = h0*gw[col] + h1*gw[col+1] + h2v*gw[col+2] + h3*gw[col+3];
    #pragma unroll
    for (int off=16; off; off>>=1) g += __shfl_xor_sync(FM, g, off);
    g += gateb[0];
    float p = __expf(g);
    int b = batch[node];
    if (lane == 0) atomicAdd(&d_gden[b], p);
    atomicAdd(&d_gnum[b*128+col],   p*h0);
    atomicAdd(&d_gnum[b*128+col+1], p*h1);
    atomicAdd(&d_gnum[b*128+col+2], p*h2v);
    atomicAdd(&d_gnum[b*128+col+3], p*h3);
}

__global__ void k_xp(const float* __restrict__ quant, const float* __restrict__ Wih,
                     const float* __restrict__ bih, const float* __restrict__ bhh){
    __shared__ float qS[TSTEPS*32];
    int b = blockIdx.x, g = threadIdx.x;
    for (int i = g; i < TSTEPS*32; i += 512) qS[i] = quant[b*TSTEPS*32 + i];
    float4 wr[8];
    #pragma unroll
    for (int q=0;q<8;q++) wr[q] = *(const float4*)&Wih[g*32 + q*4];
    float bias = bih[g] + bhh[g];
    __syncthreads();
    const float4* qS4 = (const float4*)qS;
    for (int t=0; t<TSTEPS; t++){
        float acc = bias;
        #pragma unroll
        for (int q=0;q<8;q++){
            float4 xv = qS4[t*8+q];
            acc += wr[q].x*xv.x + wr[q].y*xv.y + wr[q].z*xv.z + wr[q].w*xv.w;
        }
        d_xp[(b*TSTEPS + t)*512 + g] = acc;
    }
}

// LSTM v5: 512 threads/CTA, 2 threads per Whh row (k-split halves), W=64 regs/thread,
// double-buffered h, xp prefetch. Cluster-2 unit split + DSMEM exchange as before.
__global__ void __cluster_dims__(2,1,1) __launch_bounds__(512,1)
k_lstmp(const float* __restrict__ Whh){
    __shared__ __align__(16) float hps[2][512];
    __shared__ float gbuf[2][1024];
    int tid = threadIdx.x;
    unsigned int rank;
    asm("mov.u32 %0, %%cluster_ctarank;" : "=r"(rank));
    int U0 = (int)rank * 64;
    int b0 = (blockIdx.x >> 1) * 4;
    int rowid = tid & 255;
    int half = tid >> 8;
    int g = rowid >> 6, ju = rowid & 63;
    int row = g*128 + U0 + ju;

    union { unsigned long long u[32]; float4 v[16]; } W;
    {
        const float4* row4 = (const float4*)&Whh[row*128 + half*64];
        #pragma unroll
        for (int j=0;j<16;j++) W.v[j] = row4[j];
    }
    for (int i = tid; i < 1024; i += 512) ((float*)hps)[i] = 0.f;
    float creg = 0.f;
    __syncthreads();
    asm volatile("barrier.cluster.arrive.aligned;" ::: "memory");
    asm volatile("barrier.cluster.wait.aligned;" ::: "memory");

    unsigned int hps_addr;
    asm("{ .reg .u64 t; cvta.to.shared.u64 t, %1; cvt.u32.u64 %0, t; }" : "=r"(hps_addr) : "l"(&hps[0][0]));
    unsigned int peer = rank ^ 1u;
    unsigned int hps_peer;
    asm("mapa.shared::cluster.u32 %0, %1, %2;" : "=r"(hps_peer) : "r"(hps_addr), "r"(peer));

    int ub = (tid >> 6) & 3, uju = tid & 63;   // gate-phase mapping (tid<256)
    int hk = U0 + uju;
    int woff = (hk>>1)*8 + ub*2 + (hk&1);

    float xc0=0,xc1=0,xc2=0,xc3=0;
    if (half == 0){
        xc0 = d_xp[((b0+0)*TSTEPS + 0)*512 + row];
        xc1 = d_xp[((b0+1)*TSTEPS + 0)*512 + row];
        xc2 = d_xp[((b0+2)*TSTEPS + 0)*512 + row];
        xc3 = d_xp[((b0+3)*TSTEPS + 0)*512 + row];
    }
    int p = 0;
    for (int t=0; t<TSTEPS; t++){
        float xn0=0,xn1=0,xn2=0,xn3=0;
        if (half == 0 && t+1 < TSTEPS){
            xn0 = d_xp[((b0+0)*TSTEPS + t+1)*512 + row];
            xn1 = d_xp[((b0+1)*TSTEPS + t+1)*512 + row];
            xn2 = d_xp[((b0+2)*TSTEPS + t+1)*512 + row];
            xn3 = d_xp[((b0+3)*TSTEPS + t+1)*512 + row];
        }
        const ulonglong2* hp4 = (const ulonglong2*)&hps[p][0] + half*64;
        unsigned long long a0=0,a1=0,a2=0,a3=0;
        #pragma unroll 8
        for (int k2=0;k2<32;k2++){
            ulonglong2 hA = hp4[2*k2];
            ulonglong2 hB = hp4[2*k2+1];
            ffma2(a0, W.u[k2], hA.x);
            ffma2(a1, W.u[k2], hA.y);
            ffma2(a2, W.u[k2], hB.x);
            ffma2(a3, W.u[k2], hB.y);
        }
        float* gb = &gbuf[half][rowid*4];
        gb[0] = pairsum(a0) + xc0;
        gb[1] = pairsum(a1) + xc1;
        gb[2] = pairsum(a2) + xc2;
        gb[3] = pairsum(a3) + xc3;
        __syncthreads();
        if (tid < 256){
            int i0 = (0*64+uju)*4 + ub, i1 = (1*64+uju)*4 + ub;
            int i2 = (2*64+uju)*4 + ub, i3 = (3*64+uju)*4 + ub;
            float gi = gbuf[0][i0] + gbuf[1][i0];
            float gf = gbuf[0][i1] + gbuf[1][i1];
            float gg = gbuf[0][i2] + gbuf[1][i2];
            float go = gbuf[0][i3] + gbuf[1][i3];
            float cn = sigf(gf)*creg + sigf(gi)*tanhfa(gg);
            creg = cn;
            float hn = sigf(go)*tanhfa(cn);
            int dstoff = (p^1)*512 + woff;
            hps[p^1][woff] = hn;
            asm volatile("st.shared::cluster.f32 [%0], %1;" :: "r"(hps_peer + dstoff*4), "f"(hn) : "memory");
            if (t == TSTEPS-1) d_hT[(b0+ub)*128 + hk] = hn;
        }
        asm volatile("barrier.cluster.arrive.aligned;" ::: "memory");
        asm volatile("barrier.cluster.wait.aligned;" ::: "memory");
        p ^= 1;
        xc0 = xn0; xc1 = xn1; xc2 = xn2; xc3 = xn3;
    }
}

__global__ void k_fin(const float* __restrict__ fcW, const float* __restrict__ fcb,
                      float* __restrict__ out){
    __shared__ float r[128];
    int b = blockIdx.x, tid = threadIdx.x;
    float rep = d_gnum[b*128+tid] / (d_gden[b] + 1e-16f);
    float v = fcW[tid]*rep + fcW[128+tid]*d_hT[b*128+tid];
    r[tid] = v; __syncthreads();
    for (int off=64; off; off>>=1){
        if (tid < off) r[tid] += r[tid+off];
        __syncthreads();
    }
    if (tid == 0) out[b] = r[0] + fcb[0];
}

extern "C" void kernel_launch(void* const* d_in, const int* in_sizes, int n_in,
                              void* d_out, int out_size){
    const float* x      = (const float*)d_in[0];
    const int*   ei     = (const int*)  d_in[1];
    const int*   batch  = (const int*)  d_in[2];
    const float* quant  = (const float*)d_in[3];
    const float* gatW   = (const float*)d_in[4];
    const float* attS   = (const float*)d_in[5];
    const float* attD   = (const float*)d_in[6];
    const float* gatb   = (const float*)d_in[7];
    const float* g1     = (const float*)d_in[8];
    const float* b1     = (const float*)d_in[9];
    const float* m1     = (const float*)d_in[10];
    const float* v1     = (const float*)d_in[11];
    const float* gcnW   = (const float*)d_in[12];
    const float* gcnb   = (const float*)d_in[13];
    const float* g2     = (const float*)d_in[14];
    const float* b2     = (const float*)d_in[15];
    const float* m2     = (const float*)d_in[16];
    const float* v2     = (const float*)d_in[17];
    const float* gateW  = (const float*)d_in[18];
    const float* gateb  = (const float*)d_in[19];
    const float* Wih    = (const float*)d_in[20];
    const float* Whh    = (const float*)d_in[21];
    const float* bih    = (const float*)d_in[22];
    const float* bhh    = (const float*)d_in[23];
    const float* fcW    = (const float*)d_in[24];
    const float* fcb    = (const float*)d_in[25];
    float* out = (float*)d_out;

    cudaFuncSetAttribute(k_gemm, cudaFuncAttributeMaxDynamicSharedMemorySize, 98304);

    cudaStream_t sA, sB;
    cudaStreamCreateWithFlags(&sA, cudaStreamNonBlocking);
    cudaStreamCreateWithFlags(&sB, cudaStreamNonBlocking);
    cudaEvent_t eFork, eCsr, eLstm;
    cudaEventCreateWithFlags(&eFork, cudaEventDisableTiming);
    cudaEventCreateWithFlags(&eCsr,  cudaEventDisableTiming);
    cudaEventCreateWithFlags(&eLstm, cudaEventDisableTiming);

    cudaEventRecord(eFork, 0);
    cudaStreamWaitEvent(sA, eFork, 0);
    cudaStreamWaitEvent(sB, eFork, 0);

    // enqueue order: slot 4 (ncu capture) = k_lstmp (verify v5)
    k_xp<<<256,512,0,sB>>>(quant, Wih, bih, bhh);          // 1
    k_init<<<196,256,0,sA>>>();                            // 2
    k_count<<<3125,256,0,sA>>>(ei);                        // 3
    k_lstmp<<<128,512,0,sB>>>(Whh);                        // 4  <-- profiled
    cudaEventRecord(eLstm, sB);
    k_scan1<<<196,256,0,sA>>>();                           // 5
    k_scan2<<<1,256,0,sA>>>();                             // 6
    k_scan3<<<196,256,0,sA>>>();                           // 7
    k_prep<<<196,256,0,sA>>>();                            // 8
    k_scatter<<<3125,256,0,sA>>>(ei);                      // 9
    cudaEventRecord(eCsr, sA);
    k_gemm<<<296,256,98304>>>(x, gatW, attS, attD, 0);     // 10

    cudaStreamWaitEvent(0, eCsr, 0);
    k_gat<<<6250,256>>>(gatb, g1, b1, m1, v1);             // 11
    k_gemm<<<296,256,98304>>>(nullptr, gcnW, nullptr, nullptr, 1);  // 12
    k_gcn<<<6250,256>>>(batch, gcnb, g2, b2, m2, v2, gateW, gateb); // 13

    cudaStreamWaitEvent(0, eLstm, 0);
    k_fin<<<256,128>>>(fcW, fcb, out);                     // 14

    cudaStreamDestroy(sA);
    cudaStreamDestroy(sB);
    cudaEventDestroy(eFork);
    cudaEventDestroy(eCsr);
    cudaEventDestroy(eLstm);
    (void)in_sizes; (void)n_in; (void)out_size;
}

// round 15
// speedup vs baseline: 1.1585x; 1.1585x over previous
#include <cuda_runtime.h>
#include <cuda_fp16.h>

#define NN 50000
#define EE 800000
#define BBATCH 256
#define TSTEPS 50
#define FM 0xffffffffu

__device__ __align__(16) __half d_xwh[NN*128];
__device__ __align__(16) __half d_hwh[NN*128];
__device__ __align__(16) float d_h[NN*128];
__device__ __align__(16) float d_asrc[NN*4];
__device__ __align__(16) float d_adst[NN*4];
__device__ float d_dinv[NN];
__device__ int   d_deg[NN];
__device__ int   d_rowptr[NN+1];
__device__ int   d_cursor[NN];
__device__ int   d_colsrc[EE];
__device__ int   d_bsum[256], d_boff[256];
__device__ float d_gnum[BBATCH*128];
__device__ float d_gden[BBATCH];
__device__ __align__(16) float d_xp[BBATCH*TSTEPS*512];
__device__ float d_hT[BBATCH*128];

__device__ __forceinline__ float sigf(float x){ return __fdividef(1.f, 1.f + __expf(-x)); }
__device__ __forceinline__ float tanhfa(float x){ float e=__expf(2.f*x); return 1.f - __fdividef(2.f, e+1.f); }

__device__ __forceinline__ void ffma2(unsigned long long& d, unsigned long long a, unsigned long long b){
    asm("fma.rn.f32x2 %0, %1, %2, %0;" : "+l"(d) : "l"(a), "l"(b));
}
__device__ __forceinline__ unsigned long long dup2(float x){
    unsigned long long r;
    asm("mov.b64 %0, {%1, %1};" : "=l"(r) : "f"(x));
    return r;
}
__device__ __forceinline__ float pairsum(unsigned long long v){
    float2 f; __builtin_memcpy(&f, &v, 8); return f.x + f.y;
}
__device__ __forceinline__ float2 unpack2(unsigned long long v){
    float2 f; __builtin_memcpy(&f, &v, 8); return f;
}
__device__ __forceinline__ void h4_to_f4(uint2 u, float& a, float& b, float& c, float& d){
    __half2 h01 = *(__half2*)&u.x, h23 = *(__half2*)&u.y;
    float2 f01 = __half22float2(h01), f23 = __half22float2(h23);
    a = f01.x; b = f01.y; c = f23.x; d = f23.y;
}

__global__ void k_init(){
    int i = blockIdx.x*256 + threadIdx.x;
    if (i < NN) d_deg[i] = 0;
    if (i < BBATCH*128) d_gnum[i]=0.f;
    if (i < BBATCH) d_gden[i]=0.f;
}

__global__ void k_count(const int* __restrict__ ei){
    int i = blockIdx.x*256 + threadIdx.x;
    if (i < EE) atomicAdd(&d_deg[ei[EE+i]], 1);
}

__global__ void k_scan1(){
    __shared__ int s[256];
    int tid = threadIdx.x;
    int i = blockIdx.x*256 + tid;
    int v = (i < NN) ? d_deg[i] : 0;
    s[tid] = v; __syncthreads();
    for (int off=1; off<256; off<<=1){
        int t = (tid>=off) ? s[tid-off] : 0;
        __syncthreads(); s[tid] += t; __syncthreads();
    }
    if (i < NN) d_rowptr[i+1] = s[tid];
    if (tid == 255) d_bsum[blockIdx.x] = s[255];
}

__global__ void k_scan2(){
    __shared__ int s[256];
    int tid = threadIdx.x;
    int v = (tid < 196) ? d_bsum[tid] : 0;
    s[tid] = v; __syncthreads();
    for (int off=1; off<256; off<<=1){
        int t = (tid>=off) ? s[tid-off] : 0;
        __syncthreads(); s[tid] += t; __syncthreads();
    }
    if (tid < 196) d_boff[tid] = s[tid] - v;
}

__global__ void k_scan3(){
    int i = blockIdx.x*256 + threadIdx.x;
    if (i < NN) d_rowptr[i+1] += d_boff[blockIdx.x];
    if (i == 0) d_rowptr[0] = 0;
}

__global__ void k_prep(){
    int i = blockIdx.x*256 + threadIdx.x;
    if (i >= NN) return;
    int a = d_rowptr[i], b = d_rowptr[i+1];
    d_cursor[i] = a;
    d_dinv[i] = rsqrtf((float)(b - a + 1));
}

__global__ void k_scatter(const int* __restrict__ ei){
    int i = blockIdx.x*256 + threadIdx.x;
    if (i >= EE) return;
    int s = ei[i], d = ei[EE+i];
    int pos = atomicAdd(&d_cursor[d], 1);
    d_colsrc[pos] = s;
}

// GEMM v4 + fp16 output: Y stored as half (d_xwh mode0 / d_hwh mode1).
__global__ void __launch_bounds__(256,2) k_gemm(const float* __restrict__ Xp,
                       const float* __restrict__ W,
                       const float* __restrict__ attS, const float* __restrict__ attD, int mode){
    extern __shared__ float sm[];
    float* Ws = sm;
    float* xs = sm + 16384;
    const float* X = mode ? d_h : Xp;
    __half* Yh = mode ? d_hwh : d_xwh;
    int tid = threadIdx.x, cg = tid & 31, rg = tid >> 5;
    for (int i = tid; i < 16384; i += 256) Ws[i] = W[i];
    float as0=0,as1=0,as2=0,as3=0, ad0=0,ad1=0,ad2=0,ad3=0;
    if (!mode){
        as0=attS[cg*4]; as1=attS[cg*4+1]; as2=attS[cg*4+2]; as3=attS[cg*4+3];
        ad0=attD[cg*4]; ad1=attD[cg*4+1]; ad2=attD[cg*4+2]; ad3=attD[cg*4+3];
    }
    __syncthreads();
    const ulonglong2* Wsp = (const ulonglong2*)Ws;
    const int nchunk = (NN + 63) / 64;
    for (int chunk = blockIdx.x; chunk < nchunk; chunk += gridDim.x){
        int row0 = chunk*64;
        __syncthreads();
        for (int i = tid; i < 8192; i += 256){
            int r = i >> 7, k = i & 127;
            int gr = row0 + r;
            xs[i] = (gr < NN) ? X[gr*128 + k] : 0.f;
        }
        __syncthreads();
        unsigned long long acc[8][2];
        #pragma unroll
        for (int r=0;r<8;r++){ acc[r][0]=0ull; acc[r][1]=0ull; }
        const float* xb = xs + rg*8*128;
        #pragma unroll 4
        for (int k2=0;k2<64;k2++){
            int k = k2*2;
            ulonglong2 w0 = Wsp[k*32 + cg];
            ulonglong2 w1 = Wsp[(k+1)*32 + cg];
            #pragma unroll
            for (int r=0;r<8;r++){
                float2 xv = *(const float2*)&xb[r*128 + k];
                unsigned long long xa = dup2(xv.x);
                unsigned long long xc = dup2(xv.y);
                ffma2(acc[r][0], xa, w0.x); ffma2(acc[r][1], xa, w0.y);
                ffma2(acc[r][0], xc, w1.x); ffma2(acc[r][1], xc, w1.y);
            }
        }
        #pragma unroll
        for (int r=0;r<8;r++){
            int grow = row0 + rg*8 + r;
            float2 p01 = unpack2(acc[r][0]);
            float2 p23 = unpack2(acc[r][1]);
            if (grow < NN){
                __half2 ha = __floats2half2_rn(p01.x, p01.y);
                __half2 hb = __floats2half2_rn(p23.x, p23.y);
                uint2 u;
                u.x = *(unsigned*)&ha; u.y = *(unsigned*)&hb;
                *(uint2*)&Yh[grow*128 + cg*4] = u;
            }
            if (!mode){
                float s = p01.x*as0 + p01.y*as1 + p23.x*as2 + p23.y*as3;
                float d = p01.x*ad0 + p01.y*ad1 + p23.x*ad2 + p23.y*ad3;
                #pragma unroll
                for (int off=4; off; off>>=1){
                    s += __shfl_xor_sync(FM, s, off);
                    d += __shfl_xor_sync(FM, d, off);
                }
                if ((cg & 7) == 0 && grow < NN){
                    d_asrc[grow*4 + (cg>>3)] = s;
                    d_adst[grow*4 + (cg>>3)] = d;
                }
            }
        }
    }
}

// GAT aggregation v3: half-payload gather (8B/lane), fp32 accumulate.
__global__ void k_gat(const float* __restrict__ gatb,
                      const float* __restrict__ g1, const float* __restrict__ b1,
                      const float* __restrict__ m1, const float* __restrict__ v1){
    __shared__ float sc[128], sh[128], gb[128];
    __shared__ int   sjs[8][32];
    __shared__ __align__(16) float sex[8][32][4];
    int tid = threadIdx.x;
    if (tid < 128){
        float s = g1[tid]*rsqrtf(v1[tid]+1e-5f);
        sc[tid]=s; sh[tid]=b1[tid]-m1[tid]*s; gb[tid]=gatb[tid];
    }
    __syncthreads();
    int lane = tid & 31, w = tid >> 5;
    int node = blockIdx.x*8 + w;
    if (node >= NN) return;
    int begin = d_rowptr[node], end = d_rowptr[node+1];
    float4 adv = *(const float4*)&d_adst[node*4];
    float n0=0,n1=0,n2=0,n3=0;
    float dn0=0,dn1=0,dn2=0,dn3=0;
    for (int base = begin; base < end; base += 32){
        int idx = base + lane;
        int sl = 0; float4 exl = make_float4(0,0,0,0);
        if (idx < end){
            sl = d_colsrc[idx];
            float4 as = *(const float4*)&d_asrc[sl*4];
            float e0 = as.x+adv.x; e0 = e0>0.f? e0 : 0.2f*e0;
            float e1 = as.y+adv.y; e1 = e1>0.f? e1 : 0.2f*e1;
            float e2 = as.z+adv.z; e2 = e2>0.f? e2 : 0.2f*e2;
            float e3 = as.w+adv.w; e3 = e3>0.f? e3 : 0.2f*e3;
            exl = make_float4(__expf(e0),__expf(e1),__expf(e2),__expf(e3));
            dn0+=exl.x; dn1+=exl.y; dn2+=exl.z; dn3+=exl.w;
        }
        sjs[w][lane] = sl;
        *(float4*)sex[w][lane] = exl;
        __syncwarp();
        int cnt = min(32, end - base);
        int sj0 = sjs[w][0];
        uint2 xv = *(const uint2*)&d_xwh[sj0*128 + lane*4];
        for (int j=0; j<cnt; j++){
            uint2 xn = xv;
            if (j+1 < cnt){
                int sjn = sjs[w][j+1];
                xn = *(const uint2*)&d_xwh[sjn*128 + lane*4];
            }
            float aj = sex[w][j][lane>>3];
            float f0,f1,f2,f3; h4_to_f4(xv, f0,f1,f2,f3);
            n0 += f0*aj; n1 += f1*aj; n2 += f2*aj; n3 += f3*aj;
            xv = xn;
        }
        __syncwarp();
    }
    #pragma unroll
    for (int off=16; off; off>>=1){
        dn0 += __shfl_xor_sync(FM,dn0,off); dn1 += __shfl_xor_sync(FM,dn1,off);
        dn2 += __shfl_xor_sync(FM,dn2,off); dn3 += __shfl_xor_sync(FM,dn3,off);
    }
    float4 as = *(const float4*)&d_asrc[node*4];
    float e0=as.x+adv.x; e0=e0>0.f?e0:0.2f*e0; float x0=__expf(e0);
    float e1=as.y+adv.y; e1=e1>0.f?e1:0.2f*e1; float x1=__expf(e1);
    float e2=as.z+adv.z; e2=e2>0.f?e2:0.2f*e2; float x2=__expf(e2);
    float e3=as.w+adv.w; e3=e3>0.f?e3:0.2f*e3; float x3=__expf(e3);
    dn0+=x0; dn1+=x1; dn2+=x2; dn3+=x3;
    uint2 xu = *(const uint2*)&d_xwh[node*128 + lane*4];
    float s0,s1,s2,s3; h4_to_f4(xu, s0,s1,s2,s3);
    float aself = lane<8? x0 : lane<16? x1 : lane<24? x2 : x3;
    n0 += s0*aself; n1 += s1*aself; n2 += s2*aself; n3 += s3*aself;
    float hd = lane<8? dn0 : lane<16? dn1 : lane<24? dn2 : dn3;
    float inv = 1.0f/(hd + 1e-16f);
    int col = lane*4;
    float o0 = n0*inv + gb[col];   o0 = o0>0.f? o0 : expm1f(o0); o0 = o0*sc[col]+sh[col];
    float o1 = n1*inv + gb[col+1]; o1 = o1>0.f? o1 : expm1f(o1); o1 = o1*sc[col+1]+sh[col+1];
    float o2 = n2*inv + gb[col+2]; o2 = o2>0.f? o2 : expm1f(o2); o2 = o2*sc[col+2]+sh[col+2];
    float o3 = n3*inv + gb[col+3]; o3 = o3>0.f? o3 : expm1f(o3); o3 = o3*sc[col+3]+sh[col+3];
    *(float4*)&d_h[node*128 + col] = make_float4(o0,o1,o2,o3);
}

// GCN aggregation v3: half-payload gather.
__global__ void k_gcn(const int* __restrict__ batch,
                      const float* __restrict__ gcnb,
                      const float* __restrict__ g2, const float* __restrict__ b2,
                      const float* __restrict__ m2, const float* __restrict__ v2,
                      const float* __restrict__ gateW, const float* __restrict__ gateb){
    __shared__ float sc[128], sh[128], gb[128], gw[128];
    __shared__ int   sjs[8][32];
    __shared__ float sds[8][32];
    int tid = threadIdx.x;
    if (tid < 128){
        float s = g2[tid]*rsqrtf(v2[tid]+1e-5f);
        sc[tid]=s; sh[tid]=b2[tid]-m2[tid]*s; gb[tid]=gcnb[tid]; gw[tid]=gateW[tid];
    }
    __syncthreads();
    int lane = tid & 31, w = tid >> 5;
    int node = blockIdx.x*8 + w;
    if (node >= NN) return;
    int begin = d_rowptr[node], end = d_rowptr[node+1];
    float did = d_dinv[node];
    float a0=0,a1=0,a2=0,a3=0;
    for (int base = begin; base < end; base += 32){
        int idx = base + lane;
        int sl = 0; float dsl = 0.f;
        if (idx < end){ sl = d_colsrc[idx]; dsl = d_dinv[sl]; }
        sjs[w][lane] = sl;
        sds[w][lane] = dsl;
        __syncwarp();
        int cnt = min(32, end - base);
        int sj0 = sjs[w][0];
        uint2 xv = *(const uint2*)&d_hwh[sj0*128 + lane*4];
        for (int j=0; j<cnt; j++){
            uint2 xn = xv;
            if (j+1 < cnt){
                int sjn = sjs[w][j+1];
                xn = *(const uint2*)&d_hwh[sjn*128 + lane*4];
            }
            float dv = sds[w][j];
            float f0,f1,f2,f3; h4_to_f4(xv, f0,f1,f2,f3);
            a0 += f0*dv; a1 += f1*dv; a2 += f2*dv; a3 += f3*dv;
            xv = xn;
        }
        __syncwarp();
    }
    int col = lane*4;
    uint2 su = *(const uint2*)&d_hwh[node*128 + col];
    float v0,v1,v2s,v3; h4_to_f4(su, v0,v1,v2s,v3);
    float h0 = did*(a0 + did*v0) + gb[col];
    float h1 = did*(a1 + did*v1) + gb[col+1];
    float h2v = did*(a2 + did*v2s) + gb[col+2];
    float h3 = did*(a3 + did*v3) + gb[col+3];
    h0 = h0>0.f? h0 : expm1f(h0); h0 = h0*sc[col]+sh[col];
    h1 = h1>0.f? h1 : expm1f(h1); h1 = h1*sc[col+1]+sh[col+1];
    h2v = h2v>0.f? h2v : expm1f(h2v); h2v = h2v*sc[col+2]+sh[col+2];
    h3 = h3>0.f? h3 : expm1f(h3); h3 = h3*sc[col+3]+sh[col+3];
    float g = h0*gw[col] + h1*gw[col+1] + h2v*gw[col+2] + h3*gw[col+3];
    #pragma unroll
    for (int off=16; off; off>>=1) g += __shfl_xor_sync(FM, g, off);
    g += gateb[0];
    float p = __expf(g);
    int b = batch[node];
    if (lane == 0) atomicAdd(&d_gden[b], p);
    atomicAdd(&d_gnum[b*128+col],   p*h0);
    atomicAdd(&d_gnum[b*128+col+1], p*h1);
    atomicAdd(&d_gnum[b*128+col+2], p*h2v);
    atomicAdd(&d_gnum[b*128+col+3], p*h3);
}

__global__ void k_xp(const float* __restrict__ quant, const float* __restrict__ Wih,
                     const float* __restrict__ bih, const float* __restrict__ bhh){
    __shared__ float qS[TSTEPS*32];
    int b = blockIdx.x, g = threadIdx.x;
    for (int i = g; i < TSTEPS*32; i += 512) qS[i] = quant[b*TSTEPS*32 + i];
    float4 wr[8];
    #pragma unroll
    for (int q=0;q<8;q++) wr[q] = *(const float4*)&Wih[g*32 + q*4];
    float bias = bih[g] + bhh[g];
    __syncthreads();
    const float4* qS4 = (const float4*)qS;
    for (int t=0; t<TSTEPS; t++){
        float acc = bias;
        #pragma unroll
        for (int q=0;q<8;q++){
            float4 xv = qS4[t*8+q];
            acc += wr[q].x*xv.x + wr[q].y*xv.y + wr[q].z*xv.z + wr[q].w*xv.w;
        }
        d_xp[(b*TSTEPS + t)*512 + g] = acc;
    }
}

// LSTM v3 (reverted from v5; measured 103us in R13 build)
__global__ void __cluster_dims__(2,1,1) __launch_bounds__(256,1)
k_lstmp(const float* __restrict__ Whh){
    __shared__ __align__(16) float hps[512];
    __shared__ float gbuf[1024];
    int tid = threadIdx.x;
    unsigned int rank;
    asm("mov.u32 %0, %%cluster_ctarank;" : "=r"(rank));
    int U0 = (int)rank * 64;
    int b0 = (blockIdx.x >> 1) * 4;
    int g = tid >> 6, ju = tid & 63;
    int row = g*128 + U0 + ju;

    union { unsigned long long u[64]; float4 v[32]; } W;
    {
        const float4* row4 = (const float4*)&Whh[row*128];
        #pragma unroll
        for (int j=0;j<32;j++) W.v[j] = row4[j];
    }
    for (int i = tid; i < 512; i += 256) hps[i] = 0.f;
    float creg = 0.f;
    __syncthreads();
    asm volatile("barrier.cluster.arrive.aligned;" ::: "memory");
    asm volatile("barrier.cluster.wait.aligned;" ::: "memory");

    unsigned int hps_addr;
    asm("{ .reg .u64 t; cvta.to.shared.u64 t, %1; cvt.u32.u64 %0, t; }" : "=r"(hps_addr) : "l"(hps));
    unsigned int peer = rank ^ 1u;
    unsigned int hps_peer;
    asm("mapa.shared::cluster.u32 %0, %1, %2;" : "=r"(hps_peer) : "r"(hps_addr), "r"(peer));

    const ulonglong2* hp4 = (const ulonglong2*)hps;
    int ub = tid >> 6, uju = tid & 63;
    int hk = U0 + uju;
    int woff = (hk>>1)*8 + (ub>>1)*4 + (ub&1)*2 + (hk&1);

    for (int t=0; t<TSTEPS; t++){
        float x0 = d_xp[((b0+0)*TSTEPS + t)*512 + row];
        float x1 = d_xp[((b0+1)*TSTEPS + t)*512 + row];
        float x2 = d_xp[((b0+2)*TSTEPS + t)*512 + row];
        float x3 = d_xp[((b0+3)*TSTEPS + t)*512 + row];
        unsigned long long a0=0,a1=0,a2=0,a3=0;
        #pragma unroll
        for (int k2=0;k2<64;k2++){
            ulonglong2 hA = hp4[2*k2];
            ulonglong2 hB = hp4[2*k2+1];
            ffma2(a0, W.u[k2], hA.x);
            ffma2(a1, W.u[k2], hA.y);
            ffma2(a2, W.u[k2], hB.x);
            ffma2(a3, W.u[k2], hB.y);
        }
        ((float4*)gbuf)[tid] = make_float4(pairsum(a0)+x0, pairsum(a1)+x1,
                                           pairsum(a2)+x2, pairsum(a3)+x3);
        __syncthreads();
        float gi = gbuf[(0*64+uju)*4 + ub];
        float gf = gbuf[(1*64+uju)*4 + ub];
        float gg = gbuf[(2*64+uju)*4 + ub];
        float go = gbuf[(3*64+uju)*4 + ub];
        float cn = sigf(gf)*creg + sigf(gi)*tanhfa(gg);
        creg = cn;
        float hn = sigf(go)*tanhfa(cn);
        hps[woff] = hn;
        asm volatile("st.shared::cluster.f32 [%0], %1;" :: "r"(hps_peer + woff*4), "f"(hn) : "memory");
        if (t == TSTEPS-1) d_hT[(b0+ub)*128 + hk] = hn;
        asm volatile("barrier.cluster.arrive.aligned;" ::: "memory");
        asm volatile("barrier.cluster.wait.aligned;" ::: "memory");
    }
}

__global__ void k_fin(const float* __restrict__ fcW, const float* __restrict__ fcb,
                      float* __restrict__ out){
    __shared__ float r[128];
    int b = blockIdx.x, tid = threadIdx.x;
    float rep = d_gnum[b*128+tid] / (d_gden[b] + 1e-16f);
    float v = fcW[tid]*rep + fcW[128+tid]*d_hT[b*128+tid];
    r[tid] = v; __syncthreads();
    for (int off=64; off; off>>=1){
        if (tid < off) r[tid] += r[tid+off];
        __syncthreads();
    }
    if (tid == 0) out[b] = r[0] + fcb[0];
}

extern "C" void kernel_launch(void* const* d_in, const int* in_sizes, int n_in,
                              void* d_out, int out_size){
    const float* x      = (const float*)d_in[0];
    const int*   ei     = (const int*)  d_in[1];
    const int*   batch  = (const int*)  d_in[2];
    const float* quant  = (const float*)d_in[3];
    const float* gatW   = (const float*)d_in[4];
    const float* attS   = (const float*)d_in[5];
    const float* attD   = (const float*)d_in[6];
    const float* gatb   = (const float*)d_in[7];
    const float* g1     = (const float*)d_in[8];
    const float* b1     = (const float*)d_in[9];
    const float* m1     = (const float*)d_in[10];
    const float* v1     = (const float*)d_in[11];
    const float* gcnW   = (const float*)d_in[12];
    const float* gcnb   = (const float*)d_in[13];
    const float* g2     = (const float*)d_in[14];
    const float* b2     = (const float*)d_in[15];
    const float* m2     = (const float*)d_in[16];
    const float* v2     = (const float*)d_in[17];
    const float* gateW  = (const float*)d_in[18];
    const float* gateb  = (const float*)d_in[19];
    const float* Wih    = (const float*)d_in[20];
    const float* Whh    = (const float*)d_in[21];
    const float* bih    = (const float*)d_in[22];
    const float* bhh    = (const float*)d_in[23];
    const float* fcW    = (const float*)d_in[24];
    const float* fcb    = (const float*)d_in[25];
    float* out = (float*)d_out;

    cudaFuncSetAttribute(k_gemm, cudaFuncAttributeMaxDynamicSharedMemorySize, 98304);

    cudaStream_t sA, sB;
    cudaStreamCreateWithFlags(&sA, cudaStreamNonBlocking);
    cudaStreamCreateWithFlags(&sB, cudaStreamNonBlocking);
    cudaEvent_t eFork, eCsr, eLstm;
    cudaEventCreateWithFlags(&eFork, cudaEventDisableTiming);
    cudaEventCreateWithFlags(&eCsr,  cudaEventDisableTiming);
    cudaEventCreateWithFlags(&eLstm, cudaEventDisableTiming);

    cudaEventRecord(eFork, 0);
    cudaStreamWaitEvent(sA, eFork, 0);
    cudaStreamWaitEvent(sB, eFork, 0);

    // slot 4 (ncu capture) = k_lstmp (verify v3 restoration)
    k_xp<<<256,512,0,sB>>>(quant, Wih, bih, bhh);          // 1
    k_init<<<196,256,0,sA>>>();                            // 2
    k_count<<<3125,256,0,sA>>>(ei);                        // 3
    k_lstmp<<<128,256,0,sB>>>(Whh);                        // 4  <-- profiled
    cudaEventRecord(eLstm, sB);
    k_scan1<<<196,256,0,sA>>>();                           // 5
    k_scan2<<<1,256,0,sA>>>();                             // 6
    k_scan3<<<196,256,0,sA>>>();                           // 7
    k_prep<<<196,256,0,sA>>>();                            // 8
    k_scatter<<<3125,256,0,sA>>>(ei);                      // 9
    cudaEventRecord(eCsr, sA);
    k_gemm<<<296,256,98304>>>(x, gatW, attS, attD, 0);     // 10

    cudaStreamWaitEvent(0, eCsr, 0);
    k_gat<<<6250,256>>>(gatb, g1, b1, m1, v1);             // 11
    k_gemm<<<296,256,98304>>>(nullptr, gcnW, nullptr, nullptr, 1);  // 12
    k_gcn<<<6250,256>>>(batch, gcnb, g2, b2, m2, v2, gateW, gateb); // 13

    cudaStreamWaitEvent(0, eLstm, 0);
    k_fin<<<256,128>>>(fcW, fcb, out);                     // 14

    cudaStreamDestroy(sA);
    cudaStreamDestroy(sB);
    cudaEventDestroy(eFork);
    cudaEventDestroy(eCsr);
    cudaEventDestroy(eLstm);
    (void)in_sizes; (void)n_in; (void)out_size;
}